// round 15
// baseline (speedup 1.0000x reference)
#include <cuda_runtime.h>
#include <cstdint>

#define T_STEPS 2048
#define BATCH   64
#define H       256
#define HHALF   128
#define TBH     (T_STEPS * BATCH * H)
#define BH      (BATCH * H)

typedef unsigned long long u64;

// Scratch (no cudaMalloc allowed): packed W_ih and precomputed xproj.
__device__ u64   g_Wp[(H / 2) * H];      // Wp[u][c] = pack(W_ih[c][2u], W_ih[c][2u+1])
__device__ float g_xproj[(size_t)TBH];   // [T*B][H]

// ---------------------------------------------------------------------------
// helpers
// ---------------------------------------------------------------------------
__device__ __forceinline__ void fma2(u64& d, u64 a, u64 b)
{
    asm("fma.rn.f32x2 %0, %1, %2, %0;" : "+l"(d) : "l"(a), "l"(b));
}
__device__ __forceinline__ u64 add2(u64 a, u64 b)
{
    u64 r;
    asm("add.rn.f32x2 %0, %1, %2;" : "=l"(r) : "l"(a), "l"(b));
    return r;
}
__device__ __forceinline__ float fold2(u64 v)
{
    float lo, hi;
    asm("mov.b64 {%0, %1}, %2;" : "=f"(lo), "=f"(hi) : "l"(v));
    return lo + hi;
}
__device__ __forceinline__ uint32_t smem_u32(const void* p)
{
    uint32_t a;
    asm("{ .reg .u64 t; cvta.to.shared.u64 t, %1; cvt.u32.u64 %0, t; }"
        : "=r"(a) : "l"(p));
    return a;
}
__device__ __forceinline__ uint32_t mapa_u32(uint32_t la, uint32_t rank)
{
    uint32_t ra;
    asm("mapa.shared::cluster.u32 %0, %1, %2;" : "=r"(ra) : "r"(la), "r"(rank));
    return ra;
}
// tanh(x) = 1 - 2/(1+e^{2x}); rel err ~1e-6, graceful at large |x|.
__device__ __forceinline__ float fast_tanh(float x)
{
    float e = __expf(2.0f * x);
    return 1.0f - __fdividef(2.0f, 1.0f + e);
}

// ---------------------------------------------------------------------------
// Kernel 1: pack W_ih into pair layout (u64 transpose).
// ---------------------------------------------------------------------------
__global__ void pack_wih_kernel(const float* __restrict__ W, u64* __restrict__ Wp)
{
    __shared__ u64 tile[32][33];
    const int u0 = (blockIdx.x & 3) * 32;
    const int c0 = (blockIdx.x >> 2) * 32;
    const u64* ullW = reinterpret_cast<const u64*>(W);
    tile[threadIdx.y][threadIdx.x] = ullW[(c0 + threadIdx.y) * (H / 2) + (u0 + threadIdx.x)];
    __syncthreads();
    Wp[(u0 + threadIdx.y) * H + (c0 + threadIdx.x)] = tile[threadIdx.x][threadIdx.y];
}

// ---------------------------------------------------------------------------
// Kernel 2: xproj (256 thr, 4 rows x 8 strided cols, f32x2) — R7 version.
// ---------------------------------------------------------------------------
__global__ __launch_bounds__(256, 2)
void xproj_kernel(const float* __restrict__ x, const u64* __restrict__ Wp,
                  const float* __restrict__ b_ih, const float* __restrict__ b_hh,
                  float* __restrict__ xproj)
{
    __shared__ __align__(16) u64 xs[32][H / 2];

    const int tid = threadIdx.x;
    const size_t row0 = (size_t)blockIdx.x * 32;

    const float4* xg = reinterpret_cast<const float4*>(x + row0 * H);
    float4* xsf = reinterpret_cast<float4*>(&xs[0][0]);
    #pragma unroll
    for (int i = 0; i < 8; i++) xsf[tid + i * 256] = xg[tid + i * 256];
    __syncthreads();

    const int lane = tid & 31;
    const int rg   = tid >> 5;
    const int m0   = 4 * rg;

    u64 acc[4][8];
    #pragma unroll
    for (int m = 0; m < 4; m++)
        #pragma unroll
        for (int i = 0; i < 8; i++) acc[m][i] = 0ull;

    #pragma unroll 2
    for (int u = 0; u < H / 2; u++) {
        u64 w[8];
        #pragma unroll
        for (int i = 0; i < 8; i++) w[i] = __ldg(&Wp[u * H + lane + 32 * i]);
        #pragma unroll
        for (int m = 0; m < 4; m++) {
            u64 xv = xs[m0 + m][u];
            #pragma unroll
            for (int i = 0; i < 8; i++) fma2(acc[m][i], xv, w[i]);
        }
    }

    #pragma unroll
    for (int m = 0; m < 4; m++) {
        #pragma unroll
        for (int i = 0; i < 8; i++) {
            const int c = lane + 32 * i;
            float v = fold2(acc[m][i]) + b_ih[c] + b_hh[c];
            xproj[(row0 + m0 + m) * H + c] = v;
        }
    }
}

// ---------------------------------------------------------------------------
// Kernel 3: scan. 2-CTA cluster handles TWO batch rows, interleaved: row A's
// DSMEM transit is hidden behind row B's dot (weights shared across rows in
// registers — W_hh is batch-invariant). Partial-exchange topology per row.
// ---------------------------------------------------------------------------
__global__ void __cluster_dims__(2, 1, 1) __launch_bounds__(256, 1)
rnn_scan_kernel(const float* __restrict__ xproj, const float* __restrict__ hx,
                const float* __restrict__ W_hh, float* __restrict__ out,
                float* __restrict__ hlast)
{
    __shared__ __align__(16) float h_s[2][2][HHALF];   // [row][parity][lj]
    __shared__ __align__(16) u64 inbox[2][2][HHALF];   // [row][parity][lj]

    const int tid = threadIdx.x;
    uint32_t rank;
    asm("mov.u32 %0, %%cluster_ctarank;" : "=r"(rank));
    const int ci  = blockIdx.x >> 1;            // cluster index [0,32)
    const int bA  = 2 * ci;
    const int bB  = 2 * ci + 1;
    const int j0  = (int)rank * HHALF;          // own j/k half base
    const int jp0 = (int)(rank ^ 1u) * HHALF;   // peer j half base

    const bool sender = (tid >= HHALF);         // warps 4-7: peer-j dots
    const int  lj     = tid & (HHALF - 1);
    const int  j      = sender ? (jp0 + lj) : (j0 + lj);

    // --- weights: full 128-k chunk (own half) for my j column — shared by
    // BOTH batch rows (W_hh is batch-invariant).
    u64 w[64];
    {
        const ulonglong2* Wr = reinterpret_cast<const ulonglong2*>(
            W_hh + (size_t)j * H + j0);
        #pragma unroll
        for (int q = 0; q < 32; q++) {
            ulonglong2 v = __ldg(&Wr[q]);
            w[2 * q]     = v.x;
            w[2 * q + 1] = v.y;
        }
    }

    // --- init h (own half, both rows) + inbox tags
    if (!sender) {
        h_s[0][0][lj] = __ldg(hx + (size_t)bA * H + j0 + lj);
        h_s[1][0][lj] = __ldg(hx + (size_t)bB * H + j0 + lj);
    } else {
        u64 inv;
        asm("mov.b64 %0, {%1, %2};" : "=l"(inv) : "f"(0.0f), "r"(0xFFFFFFFFu));
        inbox[0][0][lj] = inv;
        inbox[0][1][lj] = inv;
        inbox[1][0][lj] = inv;
        inbox[1][1][lj] = inv;
    }
    __syncthreads();
    asm volatile("barrier.cluster.arrive.aligned;" ::: "memory");
    asm volatile("barrier.cluster.wait.aligned;"   ::: "memory");

    // --- addresses: inbox[row] base + par*1024
    const uint32_t inA_A = smem_u32(&inbox[0][0][lj]);
    const uint32_t inA_B = smem_u32(&inbox[1][0][lj]);
    uint32_t peerInA = 0, peerInB = 0;
    if (sender) {
        peerInA = mapa_u32(inA_A, rank ^ 1u);
        peerInB = mapa_u32(inA_B, rank ^ 1u);
    }

    // xp prefetch, 2 deep per row (receivers only)
    const float* xpbA = xproj + (size_t)bA * H + j0 + lj;
    const float* xpbB = xproj + (size_t)bB * H + j0 + lj;
    float xpA0 = 0.f, xpA1 = 0.f, xpB0 = 0.f, xpB1 = 0.f;
    if (!sender) {
        xpA0 = __ldg(xpbA);          xpB0 = __ldg(xpbB);
        xpA1 = __ldg(xpbA + BH);     xpB1 = __ldg(xpbB + BH);
    }

    float hnA = 0.0f, hnB = 0.0f;

    for (int t = 0; t < T_STEPS; t++) {
        const uint32_t par  = (uint32_t)t & 1u;
        const uint32_t ioff = par * (HHALF * 8);

        // ---- dot A (128-k, 4 chains, LDS.128, no MOVs)
        u64 a0 = 0ull, a1 = 0ull, a2 = 0ull, a3 = 0ull;
        {
            const ulonglong2* hp =
                reinterpret_cast<const ulonglong2*>(&h_s[0][par][0]);
            #pragma unroll
            for (int q = 0; q < 16; q++) {
                ulonglong2 u = hp[2 * q];
                ulonglong2 v = hp[2 * q + 1];
                fma2(a0, u.x, w[4 * q + 0]);
                fma2(a1, u.y, w[4 * q + 1]);
                fma2(a2, v.x, w[4 * q + 2]);
                fma2(a3, v.y, w[4 * q + 3]);
            }
        }
        const float pjA = fold2(add2(add2(a0, a1), add2(a2, a3)));

        if (sender) {   // fire A immediately — transit hidden behind dot B
            u64 pv;
            asm("mov.b64 %0, {%1, %2};" : "=l"(pv) : "f"(pjA), "r"((uint32_t)t));
            asm volatile("st.shared::cluster.b64 [%0], %1;"
                         :: "r"(peerInA + ioff), "l"(pv) : "memory");
        }

        // ---- dot B
        u64 c0 = 0ull, c1 = 0ull, c2 = 0ull, c3 = 0ull;
        {
            const ulonglong2* hp =
                reinterpret_cast<const ulonglong2*>(&h_s[1][par][0]);
            #pragma unroll
            for (int q = 0; q < 16; q++) {
                ulonglong2 u = hp[2 * q];
                ulonglong2 v = hp[2 * q + 1];
                fma2(c0, u.x, w[4 * q + 0]);
                fma2(c1, u.y, w[4 * q + 1]);
                fma2(c2, v.x, w[4 * q + 2]);
                fma2(c3, v.y, w[4 * q + 3]);
            }
        }
        const float pjB = fold2(add2(add2(c0, c1), add2(c2, c3)));

        if (sender) {
            u64 pv;
            asm("mov.b64 %0, {%1, %2};" : "=l"(pv) : "f"(pjB), "r"((uint32_t)t));
            asm volatile("st.shared::cluster.b64 [%0], %1;"
                         :: "r"(peerInB + ioff), "l"(pv) : "memory");
        } else {
            // ---- finish A (its DSMEM transit elapsed during dot B)
            float rv;
            {
                const uint32_t pa = inA_A + ioff;
                uint32_t lo, hi;
                do {
                    asm volatile("ld.volatile.shared.v2.u32 {%0, %1}, [%2];"
                                 : "=r"(lo), "=r"(hi) : "r"(pa) : "memory");
                } while (hi != (uint32_t)t);
                rv = __uint_as_float(lo);
            }
            hnA = fast_tanh(pjA + rv + xpA0);
            h_s[0][par ^ 1u][lj] = hnA;

            // ---- finish B
            {
                const uint32_t pa = inA_B + ioff;
                uint32_t lo, hi;
                do {
                    asm volatile("ld.volatile.shared.v2.u32 {%0, %1}, [%2];"
                                 : "=r"(lo), "=r"(hi) : "r"(pa) : "memory");
                } while (hi != (uint32_t)t);
                rv = __uint_as_float(lo);
            }
            hnB = fast_tanh(pjB + rv + xpB0);
            h_s[1][par ^ 1u][lj] = hnB;
        }
        __syncthreads();   // both rows' h[par^1] complete; inbox[par] free @t+2

        if (!sender) {
            // off-cycle: out stores + xp rotate/prefetch (both rows)
            out[(size_t)t * BH + (size_t)bA * H + j0 + lj] = hnA;
            out[(size_t)t * BH + (size_t)bB * H + j0 + lj] = hnB;
            xpA0 = xpA1;
            xpB0 = xpB1;
            if (t + 2 < T_STEPS) {
                xpA1 = __ldg(xpbA + (size_t)(t + 2) * BH);
                xpB1 = __ldg(xpbB + (size_t)(t + 2) * BH);
            }
        }
    }

    if (!sender && hlast) {
        hlast[(size_t)bA * H + j0 + lj] = hnA;
        hlast[(size_t)bB * H + j0 + lj] = hnB;
    }

    // Drain before retiring (R2 lesson: peer remote stores may be in flight).
    asm volatile("barrier.cluster.arrive.aligned;" ::: "memory");
    asm volatile("barrier.cluster.wait.aligned;"   ::: "memory");
}

// ---------------------------------------------------------------------------
extern "C" void kernel_launch(void* const* d_in, const int* in_sizes, int n_in,
                              void* d_out, int out_size)
{
    const float* x    = (const float*)d_in[0];   // [T,B,256]
    const float* hx   = (const float*)d_in[1];   // [B,256]
    const float* W_ih = (const float*)d_in[2];   // [256,256]
    const float* W_hh = (const float*)d_in[3];   // [256,256]
    const float* b_ih = (const float*)d_in[4];   // [256]
    const float* b_hh = (const float*)d_in[5];   // [256]
    float* out = (float*)d_out;

    u64*   d_Wp;
    float* d_xproj;
    cudaGetSymbolAddress((void**)&d_Wp, g_Wp);
    cudaGetSymbolAddress((void**)&d_xproj, g_xproj);

    float* hlast = (out_size >= TBH + BATCH * H) ? (out + TBH) : nullptr;

    pack_wih_kernel<<<32, dim3(32, 32)>>>(W_ih, d_Wp);
    xproj_kernel<<<(T_STEPS * BATCH) / 32, 256>>>(x, d_Wp, b_ih, b_hh, d_xproj);
    rnn_scan_kernel<<<BATCH, 256>>>(d_xproj, hx, W_hh, out, hlast);  // 32 clusters x 2 rows
    (void)in_sizes; (void)n_in;
}

// round 17
// speedup vs baseline: 1.1801x; 1.1801x over previous
#include <cuda_runtime.h>
#include <cstdint>

#define T_STEPS 2048
#define BATCH   64
#define H       256
#define HHALF   128
#define TBH     (T_STEPS * BATCH * H)
#define BH      (BATCH * H)
#define NXW     84            // xproj worker CTAs (bids 64..147)

typedef unsigned long long u64;

// Tagged xproj: each element is (f32 value, u32 tag=t+1) in one 8B word.
// Deterministic + idempotent across graph replays (stale entries from a
// previous replay hold identical values).
__device__ u64 g_xpt[(size_t)TBH];

// ---------------------------------------------------------------------------
// helpers
// ---------------------------------------------------------------------------
__device__ __forceinline__ void fma2(u64& d, u64 a, u64 b)
{
    asm("fma.rn.f32x2 %0, %1, %2, %0;" : "+l"(d) : "l"(a), "l"(b));
}
__device__ __forceinline__ u64 add2(u64 a, u64 b)
{
    u64 r;
    asm("add.rn.f32x2 %0, %1, %2;" : "=l"(r) : "l"(a), "l"(b));
    return r;
}
__device__ __forceinline__ float fold2(u64 v)
{
    float lo, hi;
    asm("mov.b64 {%0, %1}, %2;" : "=f"(lo), "=f"(hi) : "l"(v));
    return lo + hi;
}
__device__ __forceinline__ uint32_t smem_u32(const void* p)
{
    uint32_t a;
    asm("{ .reg .u64 t; cvta.to.shared.u64 t, %1; cvt.u32.u64 %0, t; }"
        : "=r"(a) : "l"(p));
    return a;
}
__device__ __forceinline__ uint32_t mapa_u32(uint32_t la, uint32_t rank)
{
    uint32_t ra;
    asm("mapa.shared::cluster.u32 %0, %1, %2;" : "=r"(ra) : "r"(la), "r"(rank));
    return ra;
}
__device__ __forceinline__ u64 vload(const u64* p)
{
    u64 v;
    asm volatile("ld.volatile.b64 %0, [%1];" : "=l"(v) : "l"(p) : "memory");
    return v;
}
__device__ __forceinline__ void vstore(u64* p, u64 v)
{
    asm volatile("st.volatile.b64 [%0], %1;" :: "l"(p), "l"(v) : "memory");
}
__device__ __forceinline__ u64 pack_tag(float f, uint32_t tag)
{
    u64 v;
    asm("mov.b64 %0, {%1, %2};" : "=l"(v) : "f"(f), "r"(tag));
    return v;
}
// tanh(x) = 1 - 2/(1+e^{2x}); rel err ~1e-6.
__device__ __forceinline__ float fast_tanh(float x)
{
    float e = __expf(2.0f * x);
    return 1.0f - __fdividef(2.0f, 1.0f + e);
}
// blocking tagged read: spin until word carries tag want, return value bits
__device__ __forceinline__ float xp_get(u64 pend, const u64* addr, uint32_t want)
{
    while ((uint32_t)(pend >> 32) != want) pend = vload(addr);
    return __uint_as_float((uint32_t)pend);
}

// ---------------------------------------------------------------------------
// THE kernel. Grid = 148 CTAs (one full wave), cluster dims (2,1,1):
//   bids 0..63   : scan — 32 clusters x 2 batch rows (R15 structure)
//   bids 64..147 : xproj producers (cluster pairs never communicate)
// ---------------------------------------------------------------------------
__global__ void __cluster_dims__(2, 1, 1) __launch_bounds__(256, 1)
rnn_mega_kernel(const float* __restrict__ x, const float* __restrict__ hx,
                const float* __restrict__ W_ih, const float* __restrict__ W_hh,
                const float* __restrict__ b_ih, const float* __restrict__ b_hh,
                float* __restrict__ out, float* __restrict__ hlast)
{
    __shared__ __align__(16) char sbuf[66560];   // 64KB x-stage | scan state
    const int tid = threadIdx.x;
    const int bid = blockIdx.x;

    if (bid >= 64) {
        // ================= XPROJ PRODUCER PATH =============================
        // worker w: j-half = w&1, slices t = (w>>1) + 42k. 42 slice-pairs.
        const int w      = bid - 64;
        const int jhalf  = w & 1;
        const int s0     = w >> 1;
        const int jl     = tid & 127;       // local j within half
        const int kh     = tid >> 7;        // k-half (2 threads per j)
        const int j      = jhalf * HHALF + jl;

        u64* xs = reinterpret_cast<u64*>(sbuf);               // [64][128] u64
        float* part = reinterpret_cast<float*>(sbuf + 65536); // [2][128]

        // weights: W_ih[j, 128*kh .. +128) as 64 u64 pairs (128 regs)
        u64 wv[64];
        {
            const ulonglong2* Wr = reinterpret_cast<const ulonglong2*>(
                W_ih + (size_t)j * H + HHALF * kh);
            #pragma unroll
            for (int q = 0; q < 32; q++) {
                ulonglong2 v = __ldg(&Wr[q]);
                wv[2 * q]     = v.x;
                wv[2 * q + 1] = v.y;
            }
        }
        float bias = 0.0f;
        if (kh == 0) bias = __ldg(b_ih + j) + __ldg(b_hh + j);

        const float4* xg4 = reinterpret_cast<const float4*>(x);
        float4* xs4 = reinterpret_cast<float4*>(xs);

        for (int t = s0; t < T_STEPS; t += NXW / 2) {
            __syncthreads();   // prior slice's xs reads complete
            // stage x[t, 0..64, :] = 4096 float4
            #pragma unroll
            for (int e = 0; e < 16; e++)
                xs4[tid + 256 * e] = xg4[(size_t)t * 4096 + tid + 256 * e];
            __syncthreads();

            for (int b = 0; b < BATCH; b++) {
                // FULL 128-float dot (R16 bug: q<8 dropped half the k-sum)
                u64 a0 = 0ull, a1 = 0ull, a2 = 0ull, a3 = 0ull;
                const ulonglong2* xv = reinterpret_cast<const ulonglong2*>(
                    &xs[b * HHALF + 64 * kh]);
                #pragma unroll
                for (int q = 0; q < 16; q++) {
                    ulonglong2 u = xv[2 * q];
                    ulonglong2 v = xv[2 * q + 1];
                    fma2(a0, u.x, wv[4 * q + 0]);
                    fma2(a1, u.y, wv[4 * q + 1]);
                    fma2(a2, v.x, wv[4 * q + 2]);
                    fma2(a3, v.y, wv[4 * q + 3]);
                }
                const float p = fold2(add2(add2(a0, a1), add2(a2, a3)));

                if (kh == 1) part[(b & 1) * HHALF + jl] = p;
                __syncthreads();
                if (kh == 0) {
                    const float v = p + part[(b & 1) * HHALF + jl] + bias;
                    vstore(&g_xpt[((size_t)t * BATCH + b) * H + j],
                           pack_tag(v, (uint32_t)t + 1u));
                }
                // part[(b&1)] next overwritten at b+2, >=1 sync away: safe
            }
        }
        return;
    }

    // ==================== SCAN PATH (R15 structure) ========================
    float (*h_s)[2][HHALF] =
        reinterpret_cast<float (*)[2][HHALF]>(sbuf);            // [2][2][128] f32
    u64 (*inbox)[2][HHALF] =
        reinterpret_cast<u64 (*)[2][HHALF]>(sbuf + 2048);       // [2][2][128] u64

    uint32_t rank;
    asm("mov.u32 %0, %%cluster_ctarank;" : "=r"(rank));
    const int ci  = bid >> 1;                   // cluster index [0,32)
    const int bA  = 2 * ci;
    const int bB  = 2 * ci + 1;
    const int j0  = (int)rank * HHALF;
    const int jp0 = (int)(rank ^ 1u) * HHALF;

    const bool sender = (tid >= HHALF);
    const int  lj     = tid & (HHALF - 1);
    const int  j      = sender ? (jp0 + lj) : (j0 + lj);

    // W_hh own-k-half chunk for my j column (shared across both rows)
    u64 w[64];
    {
        const ulonglong2* Wr = reinterpret_cast<const ulonglong2*>(
            W_hh + (size_t)j * H + j0);
        #pragma unroll
        for (int q = 0; q < 32; q++) {
            ulonglong2 v = __ldg(&Wr[q]);
            w[2 * q]     = v.x;
            w[2 * q + 1] = v.y;
        }
    }

    if (!sender) {
        h_s[0][0][lj] = __ldg(hx + (size_t)bA * H + j0 + lj);
        h_s[1][0][lj] = __ldg(hx + (size_t)bB * H + j0 + lj);
    } else {
        const u64 inv = pack_tag(0.0f, 0xFFFFFFFFu);
        inbox[0][0][lj] = inv;
        inbox[0][1][lj] = inv;
        inbox[1][0][lj] = inv;
        inbox[1][1][lj] = inv;
    }
    __syncthreads();
    asm volatile("barrier.cluster.arrive.aligned;" ::: "memory");
    asm volatile("barrier.cluster.wait.aligned;"   ::: "memory");

    const uint32_t inA_A = smem_u32(&inbox[0][0][lj]);
    const uint32_t inA_B = smem_u32(&inbox[1][0][lj]);
    uint32_t peerInA = 0, peerInB = 0;
    if (sender) {
        peerInA = mapa_u32(inA_A, rank ^ 1u);
        peerInB = mapa_u32(inA_B, rank ^ 1u);
    }

    // tagged xp prefetch, 2 deep per row (receivers only)
    const u64* xgA = g_xpt + (size_t)bA * H + j0 + lj;
    const u64* xgB = g_xpt + (size_t)bB * H + j0 + lj;
    u64 pA0 = 0, pA1 = 0, pB0 = 0, pB1 = 0;
    if (!sender) {
        pA0 = vload(xgA);            pB0 = vload(xgB);
        pA1 = vload(xgA + BH);       pB1 = vload(xgB + BH);
    }

    float hnA = 0.0f, hnB = 0.0f;

    for (int t = 0; t < T_STEPS; t++) {
        const uint32_t par  = (uint32_t)t & 1u;
        const uint32_t ioff = par * (HHALF * 8);

        // ---- dot A
        u64 a0 = 0ull, a1 = 0ull, a2 = 0ull, a3 = 0ull;
        {
            const ulonglong2* hp =
                reinterpret_cast<const ulonglong2*>(&h_s[0][par][0]);
            #pragma unroll
            for (int q = 0; q < 16; q++) {
                ulonglong2 u = hp[2 * q];
                ulonglong2 v = hp[2 * q + 1];
                fma2(a0, u.x, w[4 * q + 0]);
                fma2(a1, u.y, w[4 * q + 1]);
                fma2(a2, v.x, w[4 * q + 2]);
                fma2(a3, v.y, w[4 * q + 3]);
            }
        }
        const float pjA = fold2(add2(add2(a0, a1), add2(a2, a3)));

        if (sender) {
            asm volatile("st.shared::cluster.b64 [%0], %1;"
                         :: "r"(peerInA + ioff),
                            "l"(pack_tag(pjA, (uint32_t)t)) : "memory");
        }

        // ---- dot B
        u64 c0 = 0ull, c1 = 0ull, c2 = 0ull, c3 = 0ull;
        {
            const ulonglong2* hp =
                reinterpret_cast<const ulonglong2*>(&h_s[1][par][0]);
            #pragma unroll
            for (int q = 0; q < 16; q++) {
                ulonglong2 u = hp[2 * q];
                ulonglong2 v = hp[2 * q + 1];
                fma2(c0, u.x, w[4 * q + 0]);
                fma2(c1, u.y, w[4 * q + 1]);
                fma2(c2, v.x, w[4 * q + 2]);
                fma2(c3, v.y, w[4 * q + 3]);
            }
        }
        const float pjB = fold2(add2(add2(c0, c1), add2(c2, c3)));

        if (sender) {
            asm volatile("st.shared::cluster.b64 [%0], %1;"
                         :: "r"(peerInB + ioff),
                            "l"(pack_tag(pjB, (uint32_t)t)) : "memory");
        } else {
            // finish A (transit elapsed during dot B)
            float rv;
            {
                const uint32_t pa = inA_A + ioff;
                uint32_t lo, hi;
                do {
                    asm volatile("ld.volatile.shared.v2.u32 {%0, %1}, [%2];"
                                 : "=r"(lo), "=r"(hi) : "r"(pa) : "memory");
                } while (hi != (uint32_t)t);
                rv = __uint_as_float(lo);
            }
            const float xpA = xp_get(pA0, xgA + (size_t)t * BH, (uint32_t)t + 1u);
            hnA = fast_tanh(pjA + rv + xpA);
            h_s[0][par ^ 1u][lj] = hnA;

            // finish B
            {
                const uint32_t pa = inA_B + ioff;
                uint32_t lo, hi;
                do {
                    asm volatile("ld.volatile.shared.v2.u32 {%0, %1}, [%2];"
                                 : "=r"(lo), "=r"(hi) : "r"(pa) : "memory");
                } while (hi != (uint32_t)t);
                rv = __uint_as_float(lo);
            }
            const float xpB = xp_get(pB0, xgB + (size_t)t * BH, (uint32_t)t + 1u);
            hnB = fast_tanh(pjB + rv + xpB);
            h_s[1][par ^ 1u][lj] = hnB;
        }
        __syncthreads();

        if (!sender) {
            // off-cycle: out stores + tagged-prefetch rotate
            out[(size_t)t * BH + (size_t)bA * H + j0 + lj] = hnA;
            out[(size_t)t * BH + (size_t)bB * H + j0 + lj] = hnB;
            pA0 = pA1;
            pB0 = pB1;
            if (t + 2 < T_STEPS) {
                pA1 = vload(xgA + (size_t)(t + 2) * BH);
                pB1 = vload(xgB + (size_t)(t + 2) * BH);
            }
        }
    }

    if (!sender && hlast) {
        hlast[(size_t)bA * H + j0 + lj] = hnA;
        hlast[(size_t)bB * H + j0 + lj] = hnB;
    }

    // Drain before retiring (R2 lesson).
    asm volatile("barrier.cluster.arrive.aligned;" ::: "memory");
    asm volatile("barrier.cluster.wait.aligned;"   ::: "memory");
}

// ---------------------------------------------------------------------------
extern "C" void kernel_launch(void* const* d_in, const int* in_sizes, int n_in,
                              void* d_out, int out_size)
{
    const float* x    = (const float*)d_in[0];   // [T,B,256]
    const float* hx   = (const float*)d_in[1];   // [B,256]
    const float* W_ih = (const float*)d_in[2];   // [256,256]
    const float* W_hh = (const float*)d_in[3];   // [256,256]
    const float* b_ih = (const float*)d_in[4];   // [256]
    const float* b_hh = (const float*)d_in[5];   // [256]
    float* out = (float*)d_out;

    float* hlast = (out_size >= TBH + BATCH * H) ? (out + TBH) : nullptr;

    // One wave: 148 CTAs (64 scan + 84 xproj producers), cluster dims (2,1,1)
    rnn_mega_kernel<<<148, 256>>>(x, hx, W_ih, W_hh, b_ih, b_hh, out, hlast);
    (void)in_sizes; (void)n_in;
}